// round 11
// baseline (speedup 1.0000x reference)
#include <cuda_runtime.h>
#include <cuda_fp16.h>
#include <cstdint>

// ============================================================================
// Problem constants
// ============================================================================
#define NTOK 16384
#define DD   2048
#define NEXP 8

// GEMM tiling: CTA 128x128, 128 threads (4 warps, 2m x 2n, warp tile 64x64)
#define BM 128
#define BN 128
#define BK 64
#define THREADS 128
#define NITER (DD / BK)                 // 32 K-chunks per tile
#define NTILES_M (NTOK / BM)            // 128
#define NTILES_N (DD / BN)              // 16
#define NTILES (NTILES_M * NTILES_N)    // 2048

// SMEM layout (per CTA): B ring 3x16KB | A fp16 2x16KB | A fp32 staging 32KB
#define BTILE   16384
#define SM_B    0
#define SM_AF   (3 * BTILE)             // 49152
#define SM_STG  (SM_AF + 2 * BTILE)     // 81920
#define SMEM_TOTAL (SM_STG + 32768)     // 114688 (112KB) -> 2 CTAs = 224KB/SM

// ============================================================================
// Scratch (device globals -- allocation-free contract)
// ============================================================================
__device__ __align__(16) __half g_wcomb[(size_t)DD * DD];    // combined W, fp16
__device__ __align__(16) float  g_bcomb[DD];                 // combined bias
__device__ float g_logits[NEXP];                             // written fresh each run
__device__ float g_topw[2];
__device__ int   g_topi[2];

// ============================================================================
// PTX helpers (compute_103-safe: cp.async / ldmatrix / mma.sync only)
// ============================================================================
__device__ __forceinline__ uint32_t smem_to_u32(const void* p) {
    uint32_t a;
    asm("{ .reg .u64 t; cvta.to.shared.u64 t, %1; cvt.u32.u64 %0, t; }"
        : "=r"(a) : "l"(p));
    return a;
}

#define CP_ASYNC16(smem_u32, gptr) \
    asm volatile("cp.async.cg.shared.global [%0], [%1], 16;" \
                 :: "r"(smem_u32), "l"(gptr) : "memory")

#define CP_COMMIT() asm volatile("cp.async.commit_group;" ::: "memory")

#define STS128(addr, v0, v1, v2, v3) \
    asm volatile("st.shared.v4.b32 [%0], {%1,%2,%3,%4};" \
                 :: "r"(addr), "r"(v0), "r"(v1), "r"(v2), "r"(v3) : "memory")

#define LDMATRIX_X4(r0, r1, r2, r3, addr) \
    asm volatile("ldmatrix.sync.aligned.m8n8.x4.shared.b16 {%0,%1,%2,%3}, [%4];" \
                 : "=r"(r0), "=r"(r1), "=r"(r2), "=r"(r3) : "r"(addr))

#define MMA16816(d, a, b0, b1) \
    asm volatile("mma.sync.aligned.m16n8k16.row.col.f32.f16.f16.f32 " \
                 "{%0,%1,%2,%3}, {%4,%5,%6,%7}, {%8,%9}, {%0,%1,%2,%3};" \
                 : "+f"((d)[0]), "+f"((d)[1]), "+f"((d)[2]), "+f"((d)[3]) \
                 : "r"((a)[0]), "r"((a)[1]), "r"((a)[2]), "r"((a)[3]), \
                   "r"(b0), "r"(b1))

// ============================================================================
// Kernel 1a: gate dot products -- one block per expert, 512 threads,
//   each thread exactly one float4 (512 * 4 = 2048 = D). No atomics.
// ============================================================================
__global__ void gate_dot_kernel(const float* __restrict__ x,
                                const float* __restrict__ Wg) {
    const int e = blockIdx.x;
    float4 a = *(const float4*)(x + threadIdx.x * 4);
    float4 b = *(const float4*)(Wg + (size_t)e * DD + threadIdx.x * 4);
    float s = a.x * b.x + a.y * b.y + a.z * b.z + a.w * b.w;
    __shared__ float red[16];
    int lid = threadIdx.x & 31, wid = threadIdx.x >> 5;
    #pragma unroll
    for (int o = 16; o; o >>= 1) s += __shfl_xor_sync(0xffffffffu, s, o);
    if (lid == 0) red[wid] = s;
    __syncthreads();
    if (threadIdx.x == 0) {
        float t = 0.f;
        #pragma unroll
        for (int w = 0; w < 16; w++) t += red[w];
        g_logits[e] = t;
    }
}

// ============================================================================
// Kernel 1b: gate finalize (softmax + top-2)
// ============================================================================
__global__ void gate_fin_kernel(const float* __restrict__ bg) {
    if (threadIdx.x == 0) {
        float lg[NEXP];
        #pragma unroll
        for (int e = 0; e < NEXP; e++) lg[e] = g_logits[e] + bg[e];
        float mx = lg[0];
        #pragma unroll
        for (int e = 1; e < NEXP; e++) mx = fmaxf(mx, lg[e]);
        float p[NEXP]; float den = 0.f;
        #pragma unroll
        for (int e = 0; e < NEXP; e++) { p[e] = expf(lg[e] - mx); den += p[e]; }
        #pragma unroll
        for (int e = 0; e < NEXP; e++) p[e] /= den;
        int i0 = 0;
        #pragma unroll
        for (int e = 1; e < NEXP; e++) if (p[e] > p[i0]) i0 = e;
        int i1 = (i0 == 0) ? 1 : 0;
        #pragma unroll
        for (int e = 0; e < NEXP; e++) if (e != i0 && p[e] > p[i1]) i1 = e;
        g_topw[0] = p[i0]; g_topw[1] = p[i1];
        g_topi[0] = i0;    g_topi[1] = i1;
    }
}

// ============================================================================
// Kernel 2: combine only (W_comb = w0*We[i0] + w1*We[i1], fp16; bias fp32)
// ============================================================================
#define NBLK_CMB ((DD * DD) / (256 * 4))        // 4096

__global__ void combine_kernel(const float* __restrict__ We,
                               const float* __restrict__ be) {
    float w0 = g_topw[0], w1 = g_topw[1];
    size_t base0 = (size_t)g_topi[0] * DD * DD;
    size_t base1 = (size_t)g_topi[1] * DD * DD;
    size_t gid = (size_t)blockIdx.x * blockDim.x + threadIdx.x;
    size_t i = gid * 4;
    float4 a = *(const float4*)(We + base0 + i);
    float4 b = *(const float4*)(We + base1 + i);
    uint2 v;
    *(__half2*)&v.x = __floats2half2_rn(w0 * a.x + w1 * b.x, w0 * a.y + w1 * b.y);
    *(__half2*)&v.y = __floats2half2_rn(w0 * a.z + w1 * b.z, w0 * a.w + w1 * b.w);
    *(uint2*)(g_wcomb + i) = v;

    if (gid < DD / 4) {
        size_t j = gid * 4;
        float4 c = *(const float4*)(be + (size_t)g_topi[0] * DD + j);
        float4 d = *(const float4*)(be + (size_t)g_topi[1] * DD + j);
        float4 o;
        o.x = w0 * c.x + w1 * d.x;
        o.y = w0 * c.y + w1 * d.y;
        o.z = w0 * c.z + w1 * d.z;
        o.w = w0 * c.w + w1 * d.w;
        *(float4*)(g_bcomb + j) = o;
    }
}

// ============================================================================
// Kernel 3: persistent HMMA fp16 GEMM  out = x @ W_comb^T + b_comb
//   A read as fp32 via cp.async into a single staging buffer; converted to
//   swizzled fp16 in smem each iter (per-thread matched read/write sets make
//   the single staging buffer race-free). B via 3-ring cp.async stream.
//   Group order per iter: [staging(c+2)][B(c+2)]; wait_group 1 at iter top
//   completes B[c] and staging[c+1].
// ============================================================================
__global__ __launch_bounds__(THREADS, 2) void gemm_kernel(
        const float* __restrict__ x, float* __restrict__ out) {
    extern __shared__ char smem[];
    const uint32_t sb = smem_to_u32(smem);
    const int tid  = threadIdx.x;
    const int lane = tid & 31;
    const int wid  = tid >> 5;
    const int warp_m = wid & 1;
    const int warp_n = wid >> 1;

    // -- B loader: 16KB chunk kc of n-tile c0 into B ring slot; commits --
    auto load_b = [&](int slot, int c0, int kc) {
        uint32_t sB = sb + SM_B + slot * BTILE;
        #pragma unroll
        for (int i = 0; i < 8; i++) {
            int idx = tid + i * THREADS;
            int r = idx >> 3, c = idx & 7;
            const void* g = g_wcomb + (size_t)(c0 + r) * DD + kc + c * 8;
            CP_ASYNC16(sB + r * 128 + ((c ^ (r & 7)) << 4), g);
        }
        CP_COMMIT();
    };

    // -- A staging loader: fp32 chunk at xrow into staging (linear); commits.
    //    Thread writes fp32 pairs {j*32, j*32+16} for j = tid + k*128 --
    auto load_staging = [&](const float* xrow) {
        #pragma unroll
        for (int k = 0; k < 8; k++) {
            int j = tid + k * THREADS;
            int r = j >> 3, c = j & 7;
            const float* g = xrow + (size_t)r * DD + c * 8;
            CP_ASYNC16(sb + SM_STG + j * 32,      g);
            CP_ASYNC16(sb + SM_STG + j * 32 + 16, g + 4);
        }
        CP_COMMIT();
    };

    // -- convert staging fp32 -> swizzled fp16 A buffer (reads ONLY this
    //    thread's own staged pairs; transient registers only) --
    auto convert_a = [&](uint32_t dstA) {
        #pragma unroll
        for (int k = 0; k < 8; k++) {
            int j = tid + k * THREADS;
            int r = j >> 3, c = j & 7;
            float4 f0 = *(const float4*)(smem + SM_STG + j * 32);
            float4 f1 = *(const float4*)(smem + SM_STG + j * 32 + 16);
            uint32_t v0, v1, v2, v3;
            *(__half2*)&v0 = __floats2half2_rn(f0.x, f0.y);
            *(__half2*)&v1 = __floats2half2_rn(f0.z, f0.w);
            *(__half2*)&v2 = __floats2half2_rn(f1.x, f1.y);
            *(__half2*)&v3 = __floats2half2_rn(f1.z, f1.w);
            STS128(dstA + r * 128 + ((c ^ (r & 7)) << 4), v0, v1, v2, v3);
        }
    };

    // -- prologue-only direct convert (LDG fp32 -> fp16 STS), chunk 0 --
    auto direct_convert = [&](const float* xrow, uint32_t dstA) {
        #pragma unroll
        for (int k = 0; k < 8; k++) {
            int j = tid + k * THREADS;
            int r = j >> 3, c = j & 7;
            const float* g = xrow + (size_t)r * DD + c * 8;
            float4 f0 = *(const float4*)(g);
            float4 f1 = *(const float4*)(g + 4);
            uint32_t v0, v1, v2, v3;
            *(__half2*)&v0 = __floats2half2_rn(f0.x, f0.y);
            *(__half2*)&v1 = __floats2half2_rn(f0.z, f0.w);
            *(__half2*)&v2 = __floats2half2_rn(f1.x, f1.y);
            *(__half2*)&v3 = __floats2half2_rn(f1.z, f1.w);
            STS128(dstA + r * 128 + ((c ^ (r & 7)) << 4), v0, v1, v2, v3);
        }
    };

    // precomputed ldmatrix lane geometry
    const int a_row_lo = warp_m * 64 + (lane & 15);
    const int a_chsel  = (lane >> 4);
    const int b_row_lo = warp_n * 64 + ((lane >> 4) << 3) + (lane & 7);
    const int b_chsel  = (lane >> 3) & 1;

    int t = blockIdx.x;
    if (t >= NTILES) return;

    // prologue: queue order must be [B0, S1, B1]
    {
        const int row0 = (t >> 4) * BM;
        const int n0   = (t & 15) * BN;
        load_b(0, n0, 0);                         // B[0]
        load_staging(x + (size_t)row0 * DD + BK); // staging for chunk 1
        load_b(1, n0, BK);                        // B[1]
        direct_convert(x + (size_t)row0 * DD, sb + SM_AF);  // Afp16[0]
    }

    int stage = 0;
    float acc[4][8][4];

    while (t < NTILES) {
        const int tnext = t + gridDim.x;
        const int row0 = (t >> 4) * BM;
        const int n0   = (t & 15) * BN;

        #pragma unroll
        for (int mt = 0; mt < 4; mt++)
            #pragma unroll
            for (int nt = 0; nt < 8; nt++)
                #pragma unroll
                for (int j = 0; j < 4; j++) acc[mt][nt][j] = 0.f;

        for (int c = 0; c < NITER; c++) {
            // completes B[c] and staging[c+1]; leaves B[c+1] in flight
            asm volatile("cp.async.wait_group 1;" ::: "memory");
            // publishes B[c] + staging[c+1] + AF[(c)&1] from last convert;
            // proves all warps finished reading buffers we overwrite below.
            __syncthreads();

            // convert chunk c+1 (this tile or next tile's chunk 0)
            if (c + 1 < NITER || tnext < NTILES)
                convert_a(sb + SM_AF + ((c + 1) & 1) * BTILE);

            // issue stream chunk c+2: staging group first, then B group
            if (c + 2 < NITER) {
                load_staging(x + (size_t)row0 * DD + (c + 2) * BK);
                load_b((stage + 2) % 3, n0, (c + 2) * BK);
            } else if (tnext < NTILES) {
                const int rn0 = (tnext >> 4) * BM;
                const int nn0 = (tnext & 15) * BN;
                load_staging(x + (size_t)rn0 * DD + (c + 2 - NITER) * BK);
                load_b((stage + 2) % 3, nn0, (c + 2 - NITER) * BK);
            } else {
                CP_COMMIT();   // empty staging group
                CP_COMMIT();   // empty B group
            }

            const uint32_t sA = sb + SM_AF + (c & 1) * BTILE;
            const uint32_t sB = sb + SM_B + stage * BTILE;

            #pragma unroll
            for (int ks = 0; ks < 4; ks++) {
                uint32_t a[4][4];
                #pragma unroll
                for (int mt = 0; mt < 4; mt++) {
                    int r = a_row_lo + mt * 16;
                    int ch = (ks * 2 + a_chsel) ^ (r & 7);
                    LDMATRIX_X4(a[mt][0], a[mt][1], a[mt][2], a[mt][3],
                                sA + r * 128 + (ch << 4));
                }
                uint32_t b[4][4];
                #pragma unroll
                for (int p = 0; p < 4; p++) {
                    int r = b_row_lo + p * 16;
                    int ch = (ks * 2 + b_chsel) ^ (r & 7);
                    LDMATRIX_X4(b[p][0], b[p][1], b[p][2], b[p][3],
                                sB + r * 128 + (ch << 4));
                }
                #pragma unroll
                for (int mt = 0; mt < 4; mt++)
                    #pragma unroll
                    for (int nt = 0; nt < 8; nt++)
                        MMA16816(acc[mt][nt], a[mt],
                                 b[nt >> 1][(nt & 1) * 2],
                                 b[nt >> 1][(nt & 1) * 2 + 1]);
            }

            stage = (stage + 1) % 3;
        }

        // -- epilogue (gmem only; next tile's stream already in flight) --
        #pragma unroll
        for (int mt = 0; mt < 4; mt++) {
            int row = row0 + warp_m * 64 + mt * 16 + (lane >> 2);
            #pragma unroll
            for (int nt = 0; nt < 8; nt++) {
                int col = n0 + warp_n * 64 + nt * 8 + (lane & 3) * 2;
                float b0 = g_bcomb[col], b1 = g_bcomb[col + 1];
                float2 v0 = {acc[mt][nt][0] + b0, acc[mt][nt][1] + b1};
                float2 v1 = {acc[mt][nt][2] + b0, acc[mt][nt][3] + b1};
                *(float2*)(out + (size_t)row * DD + col) = v0;
                *(float2*)(out + (size_t)(row + 8) * DD + col) = v1;
            }
        }

        t = tnext;
    }
}

// ============================================================================
// Launch
// ============================================================================
extern "C" void kernel_launch(void* const* d_in, const int* in_sizes, int n_in,
                              void* d_out, int out_size) {
    const float* x  = (const float*)d_in[0];
    const float* Wg = (const float*)d_in[1];
    const float* bg = (const float*)d_in[2];
    const float* We = (const float*)d_in[3];
    const float* be = (const float*)d_in[4];
    float* out = (float*)d_out;

    gate_dot_kernel<<<NEXP, 512>>>(x, Wg);
    gate_fin_kernel<<<1, 32>>>(bg);
    combine_kernel<<<NBLK_CMB, 256>>>(We, be);

    int nsm = 148;
    cudaDeviceGetAttribute(&nsm, cudaDevAttrMultiProcessorCount, 0);
    int grid = 2 * nsm;
    if (grid > NTILES) grid = NTILES;

    cudaFuncSetAttribute(gemm_kernel,
                         cudaFuncAttributeMaxDynamicSharedMemorySize, SMEM_TOTAL);
    gemm_kernel<<<grid, THREADS, SMEM_TOTAL>>>(x, out);
}

// round 12
// speedup vs baseline: 1.2588x; 1.2588x over previous
#include <cuda_runtime.h>
#include <cuda_fp16.h>
#include <cstdint>

// ============================================================================
// Problem constants
// ============================================================================
#define NTOK 16384
#define DD   2048
#define NEXP 8

// GEMM tiling: CTA 128x128, 128 threads (4 warps, 2m x 2n, warp tile 64x64)
#define BM 128
#define BN 128
#define BK 64
#define THREADS 128
#define NITER (DD / BK)                 // 32 K-chunks per tile
#define NTILES_M (NTOK / BM)            // 128
#define NTILES_N (DD / BN)              // 16
#define NTILES (NTILES_M * NTILES_N)    // 2048
#define STAGE_BYTES ((BM + BN) * 128)   // 32768 per stage
#define SMEM_TOTAL (3 * STAGE_BYTES)    // 98304 (3-stage ring)

// ============================================================================
// Scratch (device globals -- allocation-free contract)
// ============================================================================
__device__ __align__(16) __half g_xh[(size_t)NTOK * DD];     // x in fp16
__device__ __align__(16) __half g_wcomb[(size_t)DD * DD];    // combined W, fp16
__device__ __align__(16) float  g_bcomb[DD];                 // combined bias
__device__ float g_logits[NEXP];                             // written fresh each run
__device__ float g_topw[2];
__device__ int   g_topi[2];

// ============================================================================
// PTX helpers (compute_103-safe: cp.async / ldmatrix / mma.sync only)
// ============================================================================
__device__ __forceinline__ uint32_t smem_to_u32(const void* p) {
    uint32_t a;
    asm("{ .reg .u64 t; cvta.to.shared.u64 t, %1; cvt.u32.u64 %0, t; }"
        : "=r"(a) : "l"(p));
    return a;
}

#define CP_ASYNC16(smem_u32, gptr) \
    asm volatile("cp.async.cg.shared.global [%0], [%1], 16;" \
                 :: "r"(smem_u32), "l"(gptr) : "memory")

#define CP_COMMIT() asm volatile("cp.async.commit_group;" ::: "memory")

#define LDMATRIX_X4(r0, r1, r2, r3, addr) \
    asm volatile("ldmatrix.sync.aligned.m8n8.x4.shared.b16 {%0,%1,%2,%3}, [%4];" \
                 : "=r"(r0), "=r"(r1), "=r"(r2), "=r"(r3) : "r"(addr))

#define MMA16816(d, a, b0, b1) \
    asm volatile("mma.sync.aligned.m16n8k16.row.col.f32.f16.f16.f32 " \
                 "{%0,%1,%2,%3}, {%4,%5,%6,%7}, {%8,%9}, {%0,%1,%2,%3};" \
                 : "+f"((d)[0]), "+f"((d)[1]), "+f"((d)[2]), "+f"((d)[3]) \
                 : "r"((a)[0]), "r"((a)[1]), "r"((a)[2]), "r"((a)[3]), \
                   "r"(b0), "r"(b1))

// ============================================================================
// Kernel 1 (fused): x fp32->fp16 convert  +  gate dot products
//   blocks [0, NBLK_CVT): convert 8 floats/thread (256 threads)
//   blocks [NBLK_CVT, NBLK_CVT+8): gate dot for one expert each
//     (256 threads x 8 floats = 2048 = D; block-reduce; direct write)
// ============================================================================
#define NBLK_CVT ((NTOK * DD) / (256 * 8))      // 16384

__global__ void cvt_gate_kernel(const float* __restrict__ x,
                                const float* __restrict__ Wg) {
    if (blockIdx.x < NBLK_CVT) {
        size_t i = ((size_t)blockIdx.x * blockDim.x + threadIdx.x) * 8;
        float4 a = *(const float4*)(x + i);
        float4 b = *(const float4*)(x + i + 4);
        uint4 v;
        *(__half2*)&v.x = __floats2half2_rn(a.x, a.y);
        *(__half2*)&v.y = __floats2half2_rn(a.z, a.w);
        *(__half2*)&v.z = __floats2half2_rn(b.x, b.y);
        *(__half2*)&v.w = __floats2half2_rn(b.z, b.w);
        *(uint4*)(g_xh + i) = v;
    } else {
        const int e = blockIdx.x - NBLK_CVT;     // expert 0..7
        const float* w = Wg + (size_t)e * DD;
        float4 a0 = *(const float4*)(x + threadIdx.x * 8);
        float4 a1 = *(const float4*)(x + threadIdx.x * 8 + 4);
        float4 b0 = *(const float4*)(w + threadIdx.x * 8);
        float4 b1 = *(const float4*)(w + threadIdx.x * 8 + 4);
        float s = a0.x * b0.x + a0.y * b0.y + a0.z * b0.z + a0.w * b0.w
                + a1.x * b1.x + a1.y * b1.y + a1.z * b1.z + a1.w * b1.w;
        __shared__ float red[8];
        int lid = threadIdx.x & 31, wid = threadIdx.x >> 5;
        #pragma unroll
        for (int o = 16; o; o >>= 1) s += __shfl_xor_sync(0xffffffffu, s, o);
        if (lid == 0) red[wid] = s;
        __syncthreads();
        if (threadIdx.x == 0) {
            float t = 0.f;
            #pragma unroll
            for (int w2 = 0; w2 < 8; w2++) t += red[w2];
            g_logits[e] = t;                     // direct write, deterministic
        }
    }
}

// ============================================================================
// Kernel 2: gate finalize (softmax + top-2)
// ============================================================================
__global__ void gate_fin_kernel(const float* __restrict__ bg) {
    if (threadIdx.x == 0) {
        float lg[NEXP];
        #pragma unroll
        for (int e = 0; e < NEXP; e++) lg[e] = g_logits[e] + bg[e];
        float mx = lg[0];
        #pragma unroll
        for (int e = 1; e < NEXP; e++) mx = fmaxf(mx, lg[e]);
        float p[NEXP]; float den = 0.f;
        #pragma unroll
        for (int e = 0; e < NEXP; e++) { p[e] = expf(lg[e] - mx); den += p[e]; }
        #pragma unroll
        for (int e = 0; e < NEXP; e++) p[e] /= den;
        int i0 = 0;
        #pragma unroll
        for (int e = 1; e < NEXP; e++) if (p[e] > p[i0]) i0 = e;
        int i1 = (i0 == 0) ? 1 : 0;
        #pragma unroll
        for (int e = 0; e < NEXP; e++) if (e != i0 && p[e] > p[i1]) i1 = e;
        g_topw[0] = p[i0]; g_topw[1] = p[i1];
        g_topi[0] = i0;    g_topi[1] = i1;
    }
}

// ============================================================================
// Kernel 3: combine (W_comb = w0*We[i0] + w1*We[i1], fp16; bias fp32)
// ============================================================================
#define NBLK_CMB ((DD * DD) / (256 * 4))        // 4096

__global__ void combine_kernel(const float* __restrict__ We,
                               const float* __restrict__ be) {
    float w0 = g_topw[0], w1 = g_topw[1];
    size_t base0 = (size_t)g_topi[0] * DD * DD;
    size_t base1 = (size_t)g_topi[1] * DD * DD;
    size_t gid = (size_t)blockIdx.x * blockDim.x + threadIdx.x;
    size_t i = gid * 4;
    float4 a = *(const float4*)(We + base0 + i);
    float4 b = *(const float4*)(We + base1 + i);
    uint2 v;
    *(__half2*)&v.x = __floats2half2_rn(w0 * a.x + w1 * b.x, w0 * a.y + w1 * b.y);
    *(__half2*)&v.y = __floats2half2_rn(w0 * a.z + w1 * b.z, w0 * a.w + w1 * b.w);
    *(uint2*)(g_wcomb + i) = v;

    if (gid < DD / 4) {
        size_t j = gid * 4;
        float4 c = *(const float4*)(be + (size_t)g_topi[0] * DD + j);
        float4 d = *(const float4*)(be + (size_t)g_topi[1] * DD + j);
        float4 o;
        o.x = w0 * c.x + w1 * d.x;
        o.y = w0 * c.y + w1 * d.y;
        o.z = w0 * c.z + w1 * d.z;
        o.w = w0 * c.w + w1 * d.w;
        *(float4*)(g_bcomb + j) = o;
    }
}

// ============================================================================
// Kernel 4: persistent HMMA fp16 GEMM  out = x_h @ W_comb^T + b_comb
//   CTA 128x128, 128 threads (2x2 warps, warp tile 64x64), 2 CTAs/SM.
//   Persistent CTAs walk tiles; cp.async chunk stream is continuous across
//   tile boundaries (no per-tile drain/refill); 3-buffer ring, wait_group 1.
//   (Byte-identical to the verified R10 gemm.)
// ============================================================================
__global__ __launch_bounds__(THREADS, 2) void gemm_kernel(float* __restrict__ out) {
    extern __shared__ char smem[];
    const uint32_t sb = smem_to_u32(smem);
    const int tid  = threadIdx.x;
    const int lane = tid & 31;
    const int wid  = tid >> 5;
    const int warp_m = wid & 1;   // 2 warp-rows over 128 rows (64 each)
    const int warp_n = wid >> 1;  // 2 warp-cols over 128 cols (64 each)

    // -- async stage loader for chunk kc of tile `tile` --
    auto load_stage = [&](int stage, int tile, int kc) {
        const int r0 = (tile >> 4) * BM;        // tile / NTILES_N
        const int c0 = (tile & 15) * BN;        // tile % NTILES_N
        uint32_t sA = sb + stage * STAGE_BYTES;
        uint32_t sB = sA + BM * 128;
        #pragma unroll
        for (int i = 0; i < 8; i++) {           // A: 1024 16B-chunks / 128 thr
            int idx = tid + i * THREADS;
            int r = idx >> 3, c = idx & 7;
            const void* g = g_xh + (size_t)(r0 + r) * DD + kc + c * 8;
            CP_ASYNC16(sA + r * 128 + ((c ^ (r & 7)) << 4), g);
        }
        #pragma unroll
        for (int i = 0; i < 8; i++) {           // B: 1024 16B-chunks / 128 thr
            int idx = tid + i * THREADS;
            int r = idx >> 3, c = idx & 7;
            const void* g = g_wcomb + (size_t)(c0 + r) * DD + kc + c * 8;
            CP_ASYNC16(sB + r * 128 + ((c ^ (r & 7)) << 4), g);
        }
        CP_COMMIT();
    };

    // precomputed ldmatrix lane geometry
    const int a_row_lo = warp_m * 64 + (lane & 15);     // + mt*16
    const int a_chsel  = (lane >> 4);                   // 0/1 -> k-lo/k-hi chunk
    const int b_row_lo = warp_n * 64 + ((lane >> 4) << 3) + (lane & 7);  // + p*16
    const int b_chsel  = (lane >> 3) & 1;

    int t = blockIdx.x;
    if (t >= NTILES) return;

    // prologue: prefetch chunks 0,1 of the first tile
    load_stage(0, t, 0);
    load_stage(1, t, BK);

    int stage = 0;
    float acc[4][8][4];

    while (t < NTILES) {
        const int tnext = t + gridDim.x;

        #pragma unroll
        for (int mt = 0; mt < 4; mt++)
            #pragma unroll
            for (int nt = 0; nt < 8; nt++)
                #pragma unroll
                for (int j = 0; j < 4; j++) acc[mt][nt][j] = 0.f;

        for (int c = 0; c < NITER; c++) {
            // continuous stream: outstanding groups at top of iter = {c, c+1};
            // wait_group 1 -> chunk c complete. Full drain only for the very
            // last chunk this CTA ever computes.
            if (c == NITER - 1 && tnext >= NTILES)
                asm volatile("cp.async.wait_group 0;" ::: "memory");
            else
                asm volatile("cp.async.wait_group 1;" ::: "memory");
            // Barrier: publishes chunk c's data; proves all warps finished
            // reading the buffer the prefetch below overwrites (chunk c-1's).
            __syncthreads();

            // prefetch chunk c+2 of the stream (this tile or the next one)
            if (c + 2 < NITER)           load_stage((stage + 2) % 3, t,     (c + 2) * BK);
            else if (tnext < NTILES)     load_stage((stage + 2) % 3, tnext, (c + 2 - NITER) * BK);

            uint32_t sA = sb + stage * STAGE_BYTES;
            uint32_t sB = sA + BM * 128;

            #pragma unroll
            for (int ks = 0; ks < 4; ks++) {
                uint32_t a[4][4];
                #pragma unroll
                for (int mt = 0; mt < 4; mt++) {
                    int r = a_row_lo + mt * 16;
                    int ch = (ks * 2 + a_chsel) ^ (r & 7);
                    LDMATRIX_X4(a[mt][0], a[mt][1], a[mt][2], a[mt][3],
                                sA + r * 128 + (ch << 4));
                }
                uint32_t b[4][4];
                #pragma unroll
                for (int p = 0; p < 4; p++) {
                    int r = b_row_lo + p * 16;
                    int ch = (ks * 2 + b_chsel) ^ (r & 7);
                    LDMATRIX_X4(b[p][0], b[p][1], b[p][2], b[p][3],
                                sB + r * 128 + (ch << 4));
                }
                #pragma unroll
                for (int mt = 0; mt < 4; mt++)
                    #pragma unroll
                    for (int nt = 0; nt < 8; nt++)
                        MMA16816(acc[mt][nt], a[mt],
                                 b[nt >> 1][(nt & 1) * 2],
                                 b[nt >> 1][(nt & 1) * 2 + 1]);
            }

            stage = (stage + 1) % 3;
        }

        // -- epilogue (gmem only; next tile's chunks 0,1 already in flight) --
        const int row0 = (t >> 4) * BM;
        const int n0   = (t & 15) * BN;
        #pragma unroll
        for (int mt = 0; mt < 4; mt++) {
            int row = row0 + warp_m * 64 + mt * 16 + (lane >> 2);
            #pragma unroll
            for (int nt = 0; nt < 8; nt++) {
                int col = n0 + warp_n * 64 + nt * 8 + (lane & 3) * 2;
                float b0 = g_bcomb[col], b1 = g_bcomb[col + 1];
                float2 v0 = {acc[mt][nt][0] + b0, acc[mt][nt][1] + b1};
                float2 v1 = {acc[mt][nt][2] + b0, acc[mt][nt][3] + b1};
                *(float2*)(out + (size_t)row * DD + col) = v0;
                *(float2*)(out + (size_t)(row + 8) * DD + col) = v1;
            }
        }

        t = tnext;
    }
}

// ============================================================================
// Launch
// ============================================================================
extern "C" void kernel_launch(void* const* d_in, const int* in_sizes, int n_in,
                              void* d_out, int out_size) {
    const float* x  = (const float*)d_in[0];
    const float* Wg = (const float*)d_in[1];
    const float* bg = (const float*)d_in[2];
    const float* We = (const float*)d_in[3];
    const float* be = (const float*)d_in[4];
    float* out = (float*)d_out;

    cvt_gate_kernel<<<NBLK_CVT + NEXP, 256>>>(x, Wg);
    gate_fin_kernel<<<1, 32>>>(bg);
    combine_kernel<<<NBLK_CMB, 256>>>(We, be);

    int nsm = 148;
    cudaDeviceGetAttribute(&nsm, cudaDevAttrMultiProcessorCount, 0);
    int grid = 2 * nsm;
    if (grid > NTILES) grid = NTILES;

    cudaFuncSetAttribute(gemm_kernel,
                         cudaFuncAttributeMaxDynamicSharedMemorySize, SMEM_TOTAL);
    gemm_kernel<<<grid, THREADS, SMEM_TOTAL>>>(out);
}

// round 13
// speedup vs baseline: 1.2634x; 1.0037x over previous
#include <cuda_runtime.h>
#include <cuda_fp16.h>
#include <cstdint>

// ============================================================================
// Problem constants
// ============================================================================
#define NTOK 16384
#define DD   2048
#define NEXP 8

// GEMM tiling: CTA 128x128, 128 threads (4 warps, 2m x 2n, warp tile 64x64)
#define BM 128
#define BN 128
#define BK 64
#define THREADS 128
#define NITER (DD / BK)                 // 32 K-chunks per tile
#define NTILES_M (NTOK / BM)            // 128
#define NTILES_N (DD / BN)              // 16
#define NTILES (NTILES_M * NTILES_N)    // 2048
#define STAGE_BYTES ((BM + BN) * 128)   // 32768 per stage
#define SMEM_TOTAL (3 * STAGE_BYTES)    // 98304 (3-stage ring)

// ============================================================================
// Scratch (device globals -- allocation-free contract)
// ============================================================================
__device__ __align__(16) __half g_xh[(size_t)NTOK * DD];     // x in fp16
__device__ __align__(16) __half g_wcomb[(size_t)DD * DD];    // combined W, fp16
__device__ __align__(16) float  g_bcomb[DD];                 // combined bias
__device__ float g_topw[2];
__device__ int   g_topi[2];

// ============================================================================
// PTX helpers (compute_103-safe: cp.async / ldmatrix / mma.sync only)
// ============================================================================
__device__ __forceinline__ uint32_t smem_to_u32(const void* p) {
    uint32_t a;
    asm("{ .reg .u64 t; cvta.to.shared.u64 t, %1; cvt.u32.u64 %0, t; }"
        : "=r"(a) : "l"(p));
    return a;
}

#define CP_ASYNC16(smem_u32, gptr) \
    asm volatile("cp.async.cg.shared.global [%0], [%1], 16;" \
                 :: "r"(smem_u32), "l"(gptr) : "memory")

#define CP_COMMIT() asm volatile("cp.async.commit_group;" ::: "memory")

#define LDMATRIX_X4(r0, r1, r2, r3, addr) \
    asm volatile("ldmatrix.sync.aligned.m8n8.x4.shared.b16 {%0,%1,%2,%3}, [%4];" \
                 : "=r"(r0), "=r"(r1), "=r"(r2), "=r"(r3) : "r"(addr))

#define MMA16816(d, a, b0, b1) \
    asm volatile("mma.sync.aligned.m16n8k16.row.col.f32.f16.f16.f32 " \
                 "{%0,%1,%2,%3}, {%4,%5,%6,%7}, {%8,%9}, {%0,%1,%2,%3};" \
                 : "+f"((d)[0]), "+f"((d)[1]), "+f"((d)[2]), "+f"((d)[3]) \
                 : "r"((a)[0]), "r"((a)[1]), "r"((a)[2]), "r"((a)[3]), \
                   "r"(b0), "r"(b1))

// ============================================================================
// Kernel 1: gate (dot + softmax + top-2) in ONE block.
//   512 threads = 8 experts x 64 threads; each thread 8 float4 (64*32=2048=D).
//   Per-expert 2-warp reduce -> thread 0 finalizes.
// ============================================================================
__global__ void gate_kernel(const float* __restrict__ x,
                            const float* __restrict__ Wg,
                            const float* __restrict__ bg) {
    const int t = threadIdx.x;              // 0..511
    const int e = t >> 6;                   // expert 0..7
    const int j = t & 63;                   // lane within expert
    const float4* x4 = (const float4*)x;
    const float4* w4 = (const float4*)(Wg + (size_t)e * DD);
    float s = 0.f;
    #pragma unroll
    for (int k = 0; k < 8; k++) {
        float4 a = x4[j + k * 64];
        float4 b = w4[j + k * 64];
        s += a.x * b.x + a.y * b.y + a.z * b.z + a.w * b.w;
    }
    #pragma unroll
    for (int o = 16; o; o >>= 1) s += __shfl_xor_sync(0xffffffffu, s, o);
    __shared__ float red[16];               // 2 warps per expert
    if ((t & 31) == 0) red[t >> 5] = s;
    __syncthreads();
    if (t == 0) {
        float lg[NEXP];
        #pragma unroll
        for (int q = 0; q < NEXP; q++) lg[q] = red[2 * q] + red[2 * q + 1] + bg[q];
        float mx = lg[0];
        #pragma unroll
        for (int q = 1; q < NEXP; q++) mx = fmaxf(mx, lg[q]);
        float p[NEXP]; float den = 0.f;
        #pragma unroll
        for (int q = 0; q < NEXP; q++) { p[q] = expf(lg[q] - mx); den += p[q]; }
        #pragma unroll
        for (int q = 0; q < NEXP; q++) p[q] /= den;
        int i0 = 0;
        #pragma unroll
        for (int q = 1; q < NEXP; q++) if (p[q] > p[i0]) i0 = q;
        int i1 = (i0 == 0) ? 1 : 0;
        #pragma unroll
        for (int q = 0; q < NEXP; q++) if (q != i0 && p[q] > p[i1]) i1 = q;
        g_topw[0] = p[i0]; g_topw[1] = p[i1];
        g_topi[0] = i0;    g_topi[1] = i1;
    }
}

// ============================================================================
// Kernel 2 (fused): x fp32->fp16 convert  +  W/b combine
//   blocks [0, NBLK_CVT): convert 8 floats/thread
//   blocks [NBLK_CVT, NBLK_CVT+NBLK_CMB): combine 4 floats/thread
//   (gate_kernel completed in a prior launch, so g_topw/g_topi are valid)
// ============================================================================
#define NBLK_CVT ((NTOK * DD) / (256 * 8))      // 16384
#define NBLK_CMB ((DD * DD) / (256 * 4))        // 4096

__global__ void prep_kernel(const float* __restrict__ x,
                            const float* __restrict__ We,
                            const float* __restrict__ be) {
    if (blockIdx.x < NBLK_CVT) {
        size_t i = ((size_t)blockIdx.x * blockDim.x + threadIdx.x) * 8;
        float4 a = *(const float4*)(x + i);
        float4 b = *(const float4*)(x + i + 4);
        uint4 v;
        *(__half2*)&v.x = __floats2half2_rn(a.x, a.y);
        *(__half2*)&v.y = __floats2half2_rn(a.z, a.w);
        *(__half2*)&v.z = __floats2half2_rn(b.x, b.y);
        *(__half2*)&v.w = __floats2half2_rn(b.z, b.w);
        *(uint4*)(g_xh + i) = v;
    } else {
        float w0 = g_topw[0], w1 = g_topw[1];
        size_t base0 = (size_t)g_topi[0] * DD * DD;
        size_t base1 = (size_t)g_topi[1] * DD * DD;
        size_t gid = (size_t)(blockIdx.x - NBLK_CVT) * blockDim.x + threadIdx.x;
        size_t i = gid * 4;
        float4 a = *(const float4*)(We + base0 + i);
        float4 b = *(const float4*)(We + base1 + i);
        uint2 v;
        *(__half2*)&v.x = __floats2half2_rn(w0 * a.x + w1 * b.x, w0 * a.y + w1 * b.y);
        *(__half2*)&v.y = __floats2half2_rn(w0 * a.z + w1 * b.z, w0 * a.w + w1 * b.w);
        *(uint2*)(g_wcomb + i) = v;

        if (gid < DD / 4) {
            size_t j = gid * 4;
            float4 c = *(const float4*)(be + (size_t)g_topi[0] * DD + j);
            float4 d = *(const float4*)(be + (size_t)g_topi[1] * DD + j);
            float4 o;
            o.x = w0 * c.x + w1 * d.x;
            o.y = w0 * c.y + w1 * d.y;
            o.z = w0 * c.z + w1 * d.z;
            o.w = w0 * c.w + w1 * d.w;
            *(float4*)(g_bcomb + j) = o;
        }
    }
}

// ============================================================================
// Kernel 3: persistent HMMA fp16 GEMM  out = x_h @ W_comb^T + b_comb
//   CTA 128x128, 128 threads (2x2 warps, warp tile 64x64), 2 CTAs/SM.
//   Persistent CTAs walk tiles; cp.async chunk stream is continuous across
//   tile boundaries (no per-tile drain/refill); 3-buffer ring, wait_group 1.
//   (Byte-identical to the verified R10 gemm.)
// ============================================================================
__global__ __launch_bounds__(THREADS, 2) void gemm_kernel(float* __restrict__ out) {
    extern __shared__ char smem[];
    const uint32_t sb = smem_to_u32(smem);
    const int tid  = threadIdx.x;
    const int lane = tid & 31;
    const int wid  = tid >> 5;
    const int warp_m = wid & 1;   // 2 warp-rows over 128 rows (64 each)
    const int warp_n = wid >> 1;  // 2 warp-cols over 128 cols (64 each)

    // -- async stage loader for chunk kc of tile `tile` --
    auto load_stage = [&](int stage, int tile, int kc) {
        const int r0 = (tile >> 4) * BM;        // tile / NTILES_N
        const int c0 = (tile & 15) * BN;        // tile % NTILES_N
        uint32_t sA = sb + stage * STAGE_BYTES;
        uint32_t sB = sA + BM * 128;
        #pragma unroll
        for (int i = 0; i < 8; i++) {           // A: 1024 16B-chunks / 128 thr
            int idx = tid + i * THREADS;
            int r = idx >> 3, c = idx & 7;
            const void* g = g_xh + (size_t)(r0 + r) * DD + kc + c * 8;
            CP_ASYNC16(sA + r * 128 + ((c ^ (r & 7)) << 4), g);
        }
        #pragma unroll
        for (int i = 0; i < 8; i++) {           // B: 1024 16B-chunks / 128 thr
            int idx = tid + i * THREADS;
            int r = idx >> 3, c = idx & 7;
            const void* g = g_wcomb + (size_t)(c0 + r) * DD + kc + c * 8;
            CP_ASYNC16(sB + r * 128 + ((c ^ (r & 7)) << 4), g);
        }
        CP_COMMIT();
    };

    // precomputed ldmatrix lane geometry
    const int a_row_lo = warp_m * 64 + (lane & 15);     // + mt*16
    const int a_chsel  = (lane >> 4);                   // 0/1 -> k-lo/k-hi chunk
    const int b_row_lo = warp_n * 64 + ((lane >> 4) << 3) + (lane & 7);  // + p*16
    const int b_chsel  = (lane >> 3) & 1;

    int t = blockIdx.x;
    if (t >= NTILES) return;

    // prologue: prefetch chunks 0,1 of the first tile
    load_stage(0, t, 0);
    load_stage(1, t, BK);

    int stage = 0;
    float acc[4][8][4];

    while (t < NTILES) {
        const int tnext = t + gridDim.x;

        #pragma unroll
        for (int mt = 0; mt < 4; mt++)
            #pragma unroll
            for (int nt = 0; nt < 8; nt++)
                #pragma unroll
                for (int j = 0; j < 4; j++) acc[mt][nt][j] = 0.f;

        for (int c = 0; c < NITER; c++) {
            // continuous stream: outstanding groups at top of iter = {c, c+1};
            // wait_group 1 -> chunk c complete. Full drain only for the very
            // last chunk this CTA ever computes.
            if (c == NITER - 1 && tnext >= NTILES)
                asm volatile("cp.async.wait_group 0;" ::: "memory");
            else
                asm volatile("cp.async.wait_group 1;" ::: "memory");
            // Barrier: publishes chunk c's data; proves all warps finished
            // reading the buffer the prefetch below overwrites (chunk c-1's).
            __syncthreads();

            // prefetch chunk c+2 of the stream (this tile or the next one)
            if (c + 2 < NITER)           load_stage((stage + 2) % 3, t,     (c + 2) * BK);
            else if (tnext < NTILES)     load_stage((stage + 2) % 3, tnext, (c + 2 - NITER) * BK);

            uint32_t sA = sb + stage * STAGE_BYTES;
            uint32_t sB = sA + BM * 128;

            #pragma unroll
            for (int ks = 0; ks < 4; ks++) {
                uint32_t a[4][4];
                #pragma unroll
                for (int mt = 0; mt < 4; mt++) {
                    int r = a_row_lo + mt * 16;
                    int ch = (ks * 2 + a_chsel) ^ (r & 7);
                    LDMATRIX_X4(a[mt][0], a[mt][1], a[mt][2], a[mt][3],
                                sA + r * 128 + (ch << 4));
                }
                uint32_t b[4][4];
                #pragma unroll
                for (int p = 0; p < 4; p++) {
                    int r = b_row_lo + p * 16;
                    int ch = (ks * 2 + b_chsel) ^ (r & 7);
                    LDMATRIX_X4(b[p][0], b[p][1], b[p][2], b[p][3],
                                sB + r * 128 + (ch << 4));
                }
                #pragma unroll
                for (int mt = 0; mt < 4; mt++)
                    #pragma unroll
                    for (int nt = 0; nt < 8; nt++)
                        MMA16816(acc[mt][nt], a[mt],
                                 b[nt >> 1][(nt & 1) * 2],
                                 b[nt >> 1][(nt & 1) * 2 + 1]);
            }

            stage = (stage + 1) % 3;
        }

        // -- epilogue (gmem only; next tile's chunks 0,1 already in flight) --
        const int row0 = (t >> 4) * BM;
        const int n0   = (t & 15) * BN;
        #pragma unroll
        for (int mt = 0; mt < 4; mt++) {
            int row = row0 + warp_m * 64 + mt * 16 + (lane >> 2);
            #pragma unroll
            for (int nt = 0; nt < 8; nt++) {
                int col = n0 + warp_n * 64 + nt * 8 + (lane & 3) * 2;
                float b0 = g_bcomb[col], b1 = g_bcomb[col + 1];
                float2 v0 = {acc[mt][nt][0] + b0, acc[mt][nt][1] + b1};
                float2 v1 = {acc[mt][nt][2] + b0, acc[mt][nt][3] + b1};
                *(float2*)(out + (size_t)row * DD + col) = v0;
                *(float2*)(out + (size_t)(row + 8) * DD + col) = v1;
            }
        }

        t = tnext;
    }
}

// ============================================================================
// Launch
// ============================================================================
extern "C" void kernel_launch(void* const* d_in, const int* in_sizes, int n_in,
                              void* d_out, int out_size) {
    const float* x  = (const float*)d_in[0];
    const float* Wg = (const float*)d_in[1];
    const float* bg = (const float*)d_in[2];
    const float* We = (const float*)d_in[3];
    const float* be = (const float*)d_in[4];
    float* out = (float*)d_out;

    gate_kernel<<<1, 512>>>(x, Wg, bg);
    prep_kernel<<<NBLK_CVT + NBLK_CMB, 256>>>(x, We, be);

    int nsm = 148;
    cudaDeviceGetAttribute(&nsm, cudaDevAttrMultiProcessorCount, 0);
    int grid = 2 * nsm;
    if (grid > NTILES) grid = NTILES;

    cudaFuncSetAttribute(gemm_kernel,
                         cudaFuncAttributeMaxDynamicSharedMemorySize, SMEM_TOTAL);
    gemm_kernel<<<grid, THREADS, SMEM_TOTAL>>>(out);
}